// round 1
// baseline (speedup 1.0000x reference)
#include <cuda_runtime.h>
#include <math.h>

#define DD 768
#define LL 256
#define NM 256          // N*M = 8*32 pairs
#define HH 3072
#define KSPLIT 4

// ---------------- scratch (device globals; no allocation allowed) ----------------
__device__ float g_q[DD];
__device__ float g_qk[DD];
__device__ float g_xbar[NM * DD];
__device__ float g_xo[NM * DD];
__device__ float g_y[NM * DD];
__device__ float g_h[NM * HH];
__device__ float g_pa[KSPLIT * NM * DD];   // GEMM A split-K partials
__device__ float g_pc[KSPLIT * NM * DD];   // GEMM C split-K partials

// ---------------- prep: q = probe @ wq^T + bq ----------------
__global__ void __launch_bounds__(256) prep_q(const float* __restrict__ probe,
                                              const float* __restrict__ wq,
                                              const float* __restrict__ bq) {
    __shared__ float sp[DD];
    for (int i = threadIdx.x; i < DD; i += 256) sp[i] = probe[i];
    __syncthreads();
    int d = blockIdx.x * 256 + threadIdx.x;   // grid 3 -> 768 threads
    const float4* w = (const float4*)(wq + (size_t)d * DD);
    float acc = 0.f;
#pragma unroll 8
    for (int e4 = 0; e4 < DD / 4; e4++) {
        float4 wv4 = w[e4];
        acc += wv4.x * sp[e4 * 4 + 0] + wv4.y * sp[e4 * 4 + 1]
             + wv4.z * sp[e4 * 4 + 2] + wv4.w * sp[e4 * 4 + 3];
    }
    g_q[d] = acc + bq[d];
}

// ---------------- prep: qk = (q @ wk) / sqrt(D)  (bk drops out of softmax) ----------------
__global__ void __launch_bounds__(256) prep_qk(const float* __restrict__ wk) {
    int e = blockIdx.x * 256 + threadIdx.x;   // grid 3
    float acc = 0.f;
#pragma unroll 8
    for (int d = 0; d < DD; d++)
        acc += g_q[d] * __ldg(wk + (size_t)d * DD + e);
    g_qk[e] = acc * rsqrtf((float)DD);
}

// ---------------- attention pool: single pass over x, online softmax ----------------
// one CTA per (n,m) pair; 8 warps, each warp owns rows l = warp, warp+8, ...
__global__ void __launch_bounds__(256) attpool(const float* __restrict__ x) {
    __shared__ float sacc[8][DD];   // 24 KB: per-warp scaled accumulators
    __shared__ float swm[8], swd[8];

    const int tid = threadIdx.x, warp = tid >> 5, lane = tid & 31;

    // each lane's fixed 24 qk elements live in registers
    float4 qkr[6];
#pragma unroll
    for (int t = 0; t < 6; t++)
        qkr[t] = ((const float4*)g_qk)[lane + 32 * t];

    const float* xp = x + (size_t)blockIdx.x * (LL * DD);

    float4 acc[6];
#pragma unroll
    for (int t = 0; t < 6; t++) acc[t] = make_float4(0.f, 0.f, 0.f, 0.f);
    float m = -INFINITY, den = 0.f;

    for (int l = warp; l < LL; l += 8) {
        const float4* row = (const float4*)(xp + (size_t)l * DD);
        float4 xv[6];
        float s = 0.f;
#pragma unroll
        for (int t = 0; t < 6; t++) {
            xv[t] = row[lane + 32 * t];
            s += xv[t].x * qkr[t].x + xv[t].y * qkr[t].y
               + xv[t].z * qkr[t].z + xv[t].w * qkr[t].w;
        }
#pragma unroll
        for (int o = 16; o > 0; o >>= 1) s += __shfl_xor_sync(0xffffffffu, s, o);

        float mn = fmaxf(m, s);
        float corr = expf(m - mn);   // first iter: exp(-inf) = 0
        float p = expf(s - mn);
        den = den * corr + p;
#pragma unroll
        for (int t = 0; t < 6; t++) {
            acc[t].x = acc[t].x * corr + p * xv[t].x;
            acc[t].y = acc[t].y * corr + p * xv[t].y;
            acc[t].z = acc[t].z * corr + p * xv[t].z;
            acc[t].w = acc[t].w * corr + p * xv[t].w;
        }
        m = mn;
    }

    // merge 8 warp states
    if (lane == 0) swm[warp] = m;
    __syncthreads();
    float gm = swm[0];
#pragma unroll
    for (int w = 1; w < 8; w++) gm = fmaxf(gm, swm[w]);
    float f = expf(m - gm);
    if (lane == 0) swd[warp] = den * f;
    float4* sa4 = (float4*)sacc[warp];
#pragma unroll
    for (int t = 0; t < 6; t++) {
        float4 v = acc[t];
        v.x *= f; v.y *= f; v.z *= f; v.w *= f;
        sa4[lane + 32 * t] = v;
    }
    __syncthreads();
    float td = 0.f;
#pragma unroll
    for (int w = 0; w < 8; w++) td += swd[w];
    float inv = 1.0f / td;
    for (int j = tid; j < DD; j += 256) {
        float s = 0.f;
#pragma unroll
        for (int w = 0; w < 8; w++) s += sacc[w][j];
        g_xbar[(size_t)blockIdx.x * DD + j] = s * inv;
    }
}

// ---------------- tiled TN SGEMM: C[m,n] (+) = A[m,:K]·B[n,:K] ----------------
// 64x64 tile, 256 threads, 4x4 per thread, optional split-K (writes partial slabs)
// mode 0: raw write (partial). mode 1: v = gelu(v + bias[n])
#define TMT 64
#define TNT 64
#define KC 16
#define SMS (TMT + 4)

__global__ void __launch_bounds__(256) gemm_tn(
    const float* __restrict__ A, const float* __restrict__ B, float* __restrict__ Cbase,
    int K, int kLen, int Nn, const float* __restrict__ bias, int mode) {
    __shared__ float As[KC][SMS];
    __shared__ float Bs[KC][SMS];
    const int t = threadIdx.x;
    const int tx = t & 15, ty = t >> 4;
    const int m0 = blockIdx.y * TMT, n0 = blockIdx.x * TNT;
    const size_t kStart = (size_t)blockIdx.z * kLen;
    float* C = Cbase + (size_t)blockIdx.z * ((size_t)NM * Nn);
    const int lr = t >> 2, lc = (t & 3) * 4;
    const float* Ap = A + (size_t)(m0 + lr) * K + kStart + lc;
    const float* Bp = B + (size_t)(n0 + lr) * K + kStart + lc;

    float acc[4][4] = {};
    for (int k0 = 0; k0 < kLen; k0 += KC) {
        float4 av = *(const float4*)(Ap + k0);
        float4 bv4 = *(const float4*)(Bp + k0);
        __syncthreads();
        As[lc + 0][lr] = av.x;  As[lc + 1][lr] = av.y;
        As[lc + 2][lr] = av.z;  As[lc + 3][lr] = av.w;
        Bs[lc + 0][lr] = bv4.x; Bs[lc + 1][lr] = bv4.y;
        Bs[lc + 2][lr] = bv4.z; Bs[lc + 3][lr] = bv4.w;
        __syncthreads();
#pragma unroll
        for (int kk = 0; kk < KC; kk++) {
            float4 a = *(const float4*)&As[kk][ty * 4];
            float4 b = *(const float4*)&Bs[kk][tx * 4];
            acc[0][0] += a.x * b.x; acc[0][1] += a.x * b.y; acc[0][2] += a.x * b.z; acc[0][3] += a.x * b.w;
            acc[1][0] += a.y * b.x; acc[1][1] += a.y * b.y; acc[1][2] += a.y * b.z; acc[1][3] += a.y * b.w;
            acc[2][0] += a.z * b.x; acc[2][1] += a.z * b.y; acc[2][2] += a.z * b.z; acc[2][3] += a.z * b.w;
            acc[3][0] += a.w * b.x; acc[3][1] += a.w * b.y; acc[3][2] += a.w * b.z; acc[3][3] += a.w * b.w;
        }
    }
#pragma unroll
    for (int i = 0; i < 4; i++) {
        int mrow = m0 + ty * 4 + i;
#pragma unroll
        for (int j = 0; j < 4; j++) {
            int nc = n0 + tx * 4 + j;
            float v = acc[i][j];
            if (mode == 1) {
                v += bias[nc];
                v = 0.5f * v * (1.0f + erff(v * 0.70710678118654752f));  // exact gelu
            }
            C[(size_t)mrow * Nn + nc] = v;
        }
    }
}

// ---------------- reduce GEMM-A partials + bias, then LayerNorm ----------------
__global__ void __launch_bounds__(256) reduce_ln(const float* __restrict__ bvec,
                                                 const float* __restrict__ gamma,
                                                 const float* __restrict__ beta) {
    const int p = blockIdx.x, tid = threadIdx.x;
    __shared__ float red[256];
    const size_t S = (size_t)NM * DD;
    float xv[3];
    float s = 0.f, ss = 0.f;
#pragma unroll
    for (int r = 0; r < 3; r++) {
        int dcol = tid + r * 256;
        size_t i = (size_t)p * DD + dcol;
        float v = g_pa[i] + g_pa[S + i] + g_pa[2 * S + i] + g_pa[3 * S + i] + bvec[dcol];
        g_xo[i] = v;
        xv[r] = v;
        s += v; ss += v * v;
    }
    red[tid] = s; __syncthreads();
    for (int o = 128; o > 0; o >>= 1) { if (tid < o) red[tid] += red[tid + o]; __syncthreads(); }
    float mu = red[0] / (float)DD;
    __syncthreads();
    red[tid] = ss; __syncthreads();
    for (int o = 128; o > 0; o >>= 1) { if (tid < o) red[tid] += red[tid + o]; __syncthreads(); }
    float var = red[0] / (float)DD - mu * mu;
    float rstd = rsqrtf(var + 1e-5f);
#pragma unroll
    for (int r = 0; r < 3; r++) {
        int dcol = tid + r * 256;
        size_t i = (size_t)p * DD + dcol;
        g_y[i] = (xv[r] - mu) * rstd * gamma[dcol] + beta[dcol];
    }
}

// ---------------- final: out = xo + (sum GEMM-C partials) + b2 ----------------
__global__ void __launch_bounds__(256) finalk(const float* __restrict__ b2,
                                              float* __restrict__ out) {
    const size_t S = (size_t)NM * DD;
    size_t i = (size_t)blockIdx.x * 256 + threadIdx.x;   // grid 768 -> 196608
    int dcol = (int)(i % DD);
    float v = g_pc[i] + g_pc[S + i] + g_pc[2 * S + i] + g_pc[3 * S + i];
    out[i] = g_xo[i] + v + b2[dcol];
}

// ---------------- launch ----------------
extern "C" void kernel_launch(void* const* d_in, const int* in_sizes, int n_in,
                              void* d_out, int out_size) {
    const float* x     = (const float*)d_in[0];
    const float* probe = (const float*)d_in[1];
    const float* wq    = (const float*)d_in[2];
    const float* bq    = (const float*)d_in[3];
    const float* wk    = (const float*)d_in[4];
    /* bk = d_in[5] unused: constant shift under softmax */
    const float* wv    = (const float*)d_in[6];
    const float* bv    = (const float*)d_in[7];
    const float* gamma = (const float*)d_in[8];
    const float* beta  = (const float*)d_in[9];
    const float* w1    = (const float*)d_in[10];
    const float* b1    = (const float*)d_in[11];
    const float* w2    = (const float*)d_in[12];
    const float* b2    = (const float*)d_in[13];
    float* out = (float*)d_out;

    float *pa, *pc, *xbar, *yb, *hb;
    cudaGetSymbolAddress((void**)&pa,   g_pa);
    cudaGetSymbolAddress((void**)&pc,   g_pc);
    cudaGetSymbolAddress((void**)&xbar, g_xbar);
    cudaGetSymbolAddress((void**)&yb,   g_y);
    cudaGetSymbolAddress((void**)&hb,   g_h);

    prep_q<<<3, 256>>>(probe, wq, bq);
    prep_qk<<<3, 256>>>(wk);
    attpool<<<NM, 256>>>(x);

    // GEMM A: xo_partial = xbar(256x768) @ wv^T(768x768), split-K=4
    gemm_tn<<<dim3(DD / TNT, NM / TMT, 4), 256>>>(xbar, wv, pa, DD, DD / 4, DD, nullptr, 0);
    reduce_ln<<<NM, 256>>>(bv, gamma, beta);

    // GEMM B: h = gelu(y(256x768) @ w1^T(3072x768) + b1), no split
    gemm_tn<<<dim3(HH / TNT, NM / TMT, 1), 256>>>(yb, w1, hb, DD, DD, HH, b1, 1);

    // GEMM C: mlp_partial = h(256x3072) @ w2^T(768x3072), split-K=4
    gemm_tn<<<dim3(DD / TNT, NM / TMT, 4), 256>>>(hb, w2, pc, HH, HH / 4, DD, nullptr, 0);

    finalk<<<(NM * DD) / 256, 256>>>(b2, out);
}